// round 4
// baseline (speedup 1.0000x reference)
#include <cuda_runtime.h>
#include <math.h>

#define NSEQ  4096
#define DIMM  1024
#define HEADS 16
#define HD    64
#define WIDTH 512
#define NW    8
#define NST   512
#define KEYW  1024

// ---------------- scratch ----------------
__device__ float g_xn[NSEQ*DIMM];
__device__ float g_qkv[NSEQ*3*DIMM];
__device__ float g_q2s[NSEQ*DIMM];
__device__ float g_state_qkv[NST*3*DIMM];
__device__ float g_st[NST*DIMM];
__device__ float g_qfs_raw[NST*DIMM];

__device__ float g_qn_main[HEADS*NSEQ*HD];
__device__ float g_kn_main[HEADS*NSEQ*HD];
__device__ float g_qn_ts[HEADS*NSEQ*HD];
__device__ float g_kn_ts[HEADS*NST*HD];
__device__ float g_qn_ss[HEADS*NST*HD];
__device__ float g_kn_ss[HEADS*NST*HD];
__device__ float g_qn_fs[HEADS*NST*HD];
__device__ float g_kn_fs[HEADS*NST*HD];

__device__ float g_attn_out[NSEQ*DIMM];
__device__ float g_ts_out[NSEQ*DIMM];
__device__ float g_state_cat[NST*2*DIMM];
__device__ float g_so[NST*DIMM];
__device__ float g_z[NST*DIMM];

// ---------------- layernorm ----------------
__global__ void __launch_bounds__(256) ln_kernel(const float* __restrict__ x,
        const float* __restrict__ gamma, const float* __restrict__ pos,
        float* __restrict__ out)
{
    int row = blockIdx.x;
    const float* xr = x + (long)row*DIMM;
    float* orow = out + (long)row*DIMM;
    __shared__ float red[256];
    float s = 0.f, s2 = 0.f;
    for (int i = threadIdx.x; i < DIMM; i += 256) { float v = xr[i]; s += v; s2 += v*v; }
    red[threadIdx.x] = s; __syncthreads();
    for (int o = 128; o; o >>= 1) { if (threadIdx.x < o) red[threadIdx.x] += red[threadIdx.x+o]; __syncthreads(); }
    float mu = red[0] * (1.f/DIMM);
    __syncthreads();
    red[threadIdx.x] = s2; __syncthreads();
    for (int o = 128; o; o >>= 1) { if (threadIdx.x < o) red[threadIdx.x] += red[threadIdx.x+o]; __syncthreads(); }
    float var = red[0] * (1.f/DIMM) - mu*mu;
    float inv = rsqrtf(var + 1e-5f);
    for (int i = threadIdx.x; i < DIMM; i += 256) {
        float v = (xr[i]-mu)*inv*gamma[i];
        if (pos) v += pos[(long)row*DIMM + i];
        orow[i] = v;
    }
}

// ---------------- TF32 helpers ----------------
__device__ __forceinline__ unsigned f2tf32(float f)
{
    unsigned r;
    asm("cvt.rna.tf32.f32 %0, %1;" : "=r"(r) : "f"(f));
    return r;
}

__device__ __forceinline__ void mma_tf32(float c[4], const unsigned a[4], const unsigned b[2])
{
    asm volatile(
        "mma.sync.aligned.m16n8k8.row.col.f32.tf32.tf32.f32 "
        "{%0,%1,%2,%3}, {%4,%5,%6,%7}, {%8,%9}, {%0,%1,%2,%3};"
        : "+f"(c[0]), "+f"(c[1]), "+f"(c[2]), "+f"(c[3])
        : "r"(a[0]), "r"(a[1]), "r"(a[2]), "r"(a[3]), "r"(b[0]), "r"(b[1]));
}

// ---------------- TF32 tensor-core GEMM ----------------
__global__ void __launch_bounds__(256) tgemm(const float* __restrict__ A,
        const float* __restrict__ B, float* __restrict__ C,
        int M, int N, int K, int accum)
{
    __shared__ unsigned As[2][16][132];
    __shared__ unsigned Bs[2][16][132];

    int tid = threadIdx.x;
    int warp = tid >> 5, lane = tid & 31;
    int wy = warp >> 1, wx = warp & 1;
    int g = lane >> 2, t4 = lane & 3;
    int m0 = blockIdx.y*128, n0 = blockIdx.x*128;

    int arow = tid >> 2;
    int acol = (tid & 3) * 4;
    int bkrow = tid >> 5;
    int bcol = lane * 4;

    const float* Abase = A + (long)(m0 + arow)*K + acol;
    const float* Bbase = B + (long)bkrow*N + n0 + bcol;

    float acc[2][8][4];
    #pragma unroll
    for (int mi = 0; mi < 2; mi++)
        #pragma unroll
        for (int nj = 0; nj < 8; nj++)
            #pragma unroll
            for (int c = 0; c < 4; c++) acc[mi][nj][c] = 0.f;

    float4 ra0, ra1, rb0, rb1;

    auto ldg = [&](int kt) {
        ra0 = *(const float4*)(Abase + kt*16);
        ra1 = *(const float4*)(Abase + kt*16 + (long)64*K);
        rb0 = *(const float4*)(Bbase + (long)kt*16*N);
        rb1 = *(const float4*)(Bbase + (long)(kt*16+8)*N);
    };
    auto sts = [&](int buf) {
        As[buf][acol+0][arow] = f2tf32(ra0.x);
        As[buf][acol+1][arow] = f2tf32(ra0.y);
        As[buf][acol+2][arow] = f2tf32(ra0.z);
        As[buf][acol+3][arow] = f2tf32(ra0.w);
        As[buf][acol+0][arow+64] = f2tf32(ra1.x);
        As[buf][acol+1][arow+64] = f2tf32(ra1.y);
        As[buf][acol+2][arow+64] = f2tf32(ra1.z);
        As[buf][acol+3][arow+64] = f2tf32(ra1.w);
        Bs[buf][bkrow][bcol+0] = f2tf32(rb0.x);
        Bs[buf][bkrow][bcol+1] = f2tf32(rb0.y);
        Bs[buf][bkrow][bcol+2] = f2tf32(rb0.z);
        Bs[buf][bkrow][bcol+3] = f2tf32(rb0.w);
        Bs[buf][bkrow+8][bcol+0] = f2tf32(rb1.x);
        Bs[buf][bkrow+8][bcol+1] = f2tf32(rb1.y);
        Bs[buf][bkrow+8][bcol+2] = f2tf32(rb1.z);
        Bs[buf][bkrow+8][bcol+3] = f2tf32(rb1.w);
    };

    ldg(0); sts(0);
    __syncthreads();

    int nkt = K >> 4;
    for (int kt = 0; kt < nkt; kt++) {
        int buf = kt & 1;
        if (kt + 1 < nkt) ldg(kt + 1);

        #pragma unroll
        for (int ks = 0; ks < 2; ks++) {
            int kk = ks*8;
            unsigned af[2][4], bf[8][2];
            #pragma unroll
            for (int mi = 0; mi < 2; mi++) {
                int mr = wy*32 + mi*16 + g;
                af[mi][0] = As[buf][kk + t4][mr];
                af[mi][1] = As[buf][kk + t4][mr + 8];
                af[mi][2] = As[buf][kk + t4 + 4][mr];
                af[mi][3] = As[buf][kk + t4 + 4][mr + 8];
            }
            #pragma unroll
            for (int nj = 0; nj < 8; nj++) {
                int nc = wx*64 + nj*8 + g;
                bf[nj][0] = Bs[buf][kk + t4][nc];
                bf[nj][1] = Bs[buf][kk + t4 + 4][nc];
            }
            #pragma unroll
            for (int mi = 0; mi < 2; mi++)
                #pragma unroll
                for (int nj = 0; nj < 8; nj++)
                    mma_tf32(acc[mi][nj], af[mi], bf[nj]);
        }

        if (kt + 1 < nkt) sts(buf ^ 1);
        __syncthreads();
    }

    #pragma unroll
    for (int mi = 0; mi < 2; mi++) {
        #pragma unroll
        for (int nj = 0; nj < 8; nj++) {
            int row = m0 + wy*32 + mi*16 + g;
            int col = n0 + wx*64 + nj*8 + t4*2;
            float* p0 = &C[(long)row*N + col];
            float* p1 = &C[(long)(row+8)*N + col];
            float2 v0 = make_float2(acc[mi][nj][0], acc[mi][nj][1]);
            float2 v1 = make_float2(acc[mi][nj][2], acc[mi][nj][3]);
            if (accum) {
                float2 o0 = *(float2*)p0, o1 = *(float2*)p1;
                v0.x += o0.x; v0.y += o0.y; v1.x += o1.x; v1.y += o1.y;
            }
            *(float2*)p0 = v0;
            *(float2*)p1 = v1;
        }
    }
}

// ---------------- l2norm + scale, head-major ----------------
__global__ void norm_heads(const float* __restrict__ src, int srcStride, int colOff,
        int rowOff, const float* __restrict__ scale, float* __restrict__ dst, int nrows)
{
    int row = blockIdx.x, h = blockIdx.y, d = threadIdx.x;
    float v = src[(long)(rowOff+row)*srcStride + colOff + h*HD + d];
    float s = v*v;
    #pragma unroll
    for (int o = 16; o; o >>= 1) s += __shfl_xor_sync(0xffffffffu, s, o);
    __shared__ float sh[2];
    if ((d & 31) == 0) sh[d>>5] = s;
    __syncthreads();
    float inv = 1.f / fmaxf(sqrtf(sh[0]+sh[1]), 1e-12f);
    dst[((long)h*nrows + row)*HD + d] = v*inv*scale[d];
}

// ---------------- flash attention with compensated TF32 MMA ----------------
#define FPAD 68
#define TILEU (64*FPAD)
#define FLASH_SMEM (8*TILEU*4 + 256*4)

__global__ void __launch_bounds__(256) flashmma(
        const float* __restrict__ Q, int qHeadRows,
        const float* __restrict__ Kh, int kHeadRows,
        const float* __restrict__ Vall, long vstride, int vColHeadMul, int vColAdd,
        int vRowExtra,
        const float* __restrict__ bias,
        float* __restrict__ Out, long ostride, int oColMul, int oColAdd,
        int L, int nwin)
{
    extern __shared__ unsigned usm[];
    unsigned* QHI = usm;
    unsigned* QLO = usm + TILEU;
    unsigned* KHI = usm + 2*TILEU;
    unsigned* KLO = usm + 3*TILEU;
    unsigned* VHI = usm + 4*TILEU;
    unsigned* VLO = usm + 5*TILEU;
    unsigned* PHI = usm + 6*TILEU;
    unsigned* PLO = usm + 7*TILEU;
    float* SMAX = (float*)(usm + 8*TILEU);   // [64][2]
    float* SSUM = SMAX + 128;                // [64][2]

    int tid = threadIdx.x;
    int warp = tid >> 5, lane = tid & 31;
    int wy = warp >> 1, wx = warp & 1;
    int g = lane >> 2, t4 = lane & 3;

    int z = blockIdx.y;
    int h = z / nwin, w = z - h*nwin;
    int winw = qHeadRows / nwin;
    int i0 = blockIdx.x*64;
    int qrow0 = w*winw + i0;
    int kOff = (nwin > 1) ? (w-1)*winw : 0;

    const float* Qblk = Q + ((long)h*qHeadRows + qrow0)*64;
    const float* Kbase = Kh + (long)h*kHeadRows*64;
    const float* Vbase = Vall + vColHeadMul*h + vColAdd;
    const float* biasH = bias ? bias + (long)h*WIDTH*KEYW : nullptr;

    // load Q, split hi/lo, store [d][row]
    #pragma unroll
    for (int t = 0; t < 16; t++) {
        int e = tid + t*256;
        int r = e >> 6, c = e & 63;
        float v = Qblk[(long)r*64 + c];
        unsigned hi = f2tf32(v);
        QHI[c*FPAD + r] = hi;
        QLO[c*FPAD + r] = f2tf32(v - __uint_as_float(hi));
    }

    int mr = wy*16 + g;                      // output rows mr, mr+8
    float m0r = -3.402823466e38f, m1r = -3.402823466e38f;
    float l0 = 0.f, l1 = 0.f;
    float acc[4][4];
    #pragma unroll
    for (int nj = 0; nj < 4; nj++)
        #pragma unroll
        for (int c = 0; c < 4; c++) acc[nj][c] = 0.f;

    int Lq = biasH ? (i0 + 576) : L;
    if (Lq > L) Lq = L;

    for (int c0 = 0; c0 < Lq; c0 += 64) {
        // load + split K [d][key] and V [key][d]
        #pragma unroll
        for (int t = 0; t < 16; t++) {
            int e = tid + t*256;
            int r = e >> 6, cc = e & 63;
            int kr = kOff + c0 + r;
            float kv = (kr >= 0) ? Kbase[(long)kr*64 + cc] : 0.f;
            float vv = (kr >= 0) ? Vbase[(long)(kr + vRowExtra)*vstride + cc] : 0.f;
            unsigned khi = f2tf32(kv);
            KHI[cc*FPAD + r] = khi;
            KLO[cc*FPAD + r] = f2tf32(kv - __uint_as_float(khi));
            unsigned vhi = f2tf32(vv);
            VHI[r*FPAD + cc] = vhi;
            VLO[r*FPAD + cc] = f2tf32(vv - __uint_as_float(vhi));
        }
        __syncthreads();

        // ---- S = Q @ K^T (compensated) ----
        float sf[4][4];
        #pragma unroll
        for (int nj = 0; nj < 4; nj++)
            #pragma unroll
            for (int c = 0; c < 4; c++) sf[nj][c] = 0.f;

        #pragma unroll
        for (int kk = 0; kk < 64; kk += 8) {
            unsigned ahi[4], alo[4];
            ahi[0] = QHI[(kk+t4)*FPAD + mr];
            ahi[1] = QHI[(kk+t4)*FPAD + mr + 8];
            ahi[2] = QHI[(kk+t4+4)*FPAD + mr];
            ahi[3] = QHI[(kk+t4+4)*FPAD + mr + 8];
            alo[0] = QLO[(kk+t4)*FPAD + mr];
            alo[1] = QLO[(kk+t4)*FPAD + mr + 8];
            alo[2] = QLO[(kk+t4+4)*FPAD + mr];
            alo[3] = QLO[(kk+t4+4)*FPAD + mr + 8];
            #pragma unroll
            for (int nj = 0; nj < 4; nj++) {
                int nc = wx*32 + nj*8 + g;
                unsigned bhi[2] = { KHI[(kk+t4)*FPAD + nc], KHI[(kk+t4+4)*FPAD + nc] };
                unsigned blo[2] = { KLO[(kk+t4)*FPAD + nc], KLO[(kk+t4+4)*FPAD + nc] };
                mma_tf32(sf[nj], ahi, bhi);
                mma_tf32(sf[nj], alo, bhi);
                mma_tf32(sf[nj], ahi, blo);
            }
        }

        // ---- scale + bias + mask ----
        int ir0 = i0 + mr, ir1 = ir0 + 8;
        #pragma unroll
        for (int nj = 0; nj < 4; nj++) {
            int j0 = c0 + wx*32 + nj*8 + 2*t4;
            #pragma unroll
            for (int c = 0; c < 4; c++) sf[nj][c] *= 8.f;
            if (biasH) {
                float2 b0 = *(const float2*)&biasH[(long)ir0*KEYW + j0];
                float2 b1 = *(const float2*)&biasH[(long)ir1*KEYW + j0];
                sf[nj][0] += b0.x; sf[nj][1] += b0.y;
                sf[nj][2] += b1.x; sf[nj][3] += b1.y;
                if (j0     > ir0 + 512) sf[nj][0] = -3.402823466e38f;
                if (j0 + 1 > ir0 + 512) sf[nj][1] = -3.402823466e38f;
                if (j0     > ir1 + 512) sf[nj][2] = -3.402823466e38f;
                if (j0 + 1 > ir1 + 512) sf[nj][3] = -3.402823466e38f;
            }
        }

        // ---- row max: per-thread partial, t4-shfl, cross-wx via SMEM ----
        float pm0 = -3.402823466e38f, pm1 = -3.402823466e38f;
        #pragma unroll
        for (int nj = 0; nj < 4; nj++) {
            pm0 = fmaxf(pm0, fmaxf(sf[nj][0], sf[nj][1]));
            pm1 = fmaxf(pm1, fmaxf(sf[nj][2], sf[nj][3]));
        }
        pm0 = fmaxf(pm0, __shfl_xor_sync(0xffffffffu, pm0, 1));
        pm0 = fmaxf(pm0, __shfl_xor_sync(0xffffffffu, pm0, 2));
        pm1 = fmaxf(pm1, __shfl_xor_sync(0xffffffffu, pm1, 1));
        pm1 = fmaxf(pm1, __shfl_xor_sync(0xffffffffu, pm1, 2));
        if (t4 == 0) {
            SMAX[mr*2 + wx] = pm0;
            SMAX[(mr+8)*2 + wx] = pm1;
        }
        __syncthreads();
        float cmax0 = fmaxf(SMAX[mr*2], SMAX[mr*2+1]);
        float cmax1 = fmaxf(SMAX[(mr+8)*2], SMAX[(mr+8)*2+1]);

        float mn0 = fmaxf(m0r, cmax0);
        float mn1 = fmaxf(m1r, cmax1);
        float corr0 = __expf(m0r - mn0);
        float corr1 = __expf(m1r - mn1);
        m0r = mn0; m1r = mn1;

        // exp + partial sums + write P (split, transposed [key][row])
        float ps0 = 0.f, ps1 = 0.f;
        #pragma unroll
        for (int nj = 0; nj < 4; nj++) {
            int j0 = wx*32 + nj*8 + 2*t4;
            float p00 = __expf(sf[nj][0] - mn0);
            float p01 = __expf(sf[nj][1] - mn0);
            float p10 = __expf(sf[nj][2] - mn1);
            float p11 = __expf(sf[nj][3] - mn1);
            ps0 += p00 + p01;
            ps1 += p10 + p11;
            unsigned hi;
            hi = f2tf32(p00); PHI[j0*FPAD + mr] = hi;     PLO[j0*FPAD + mr]     = f2tf32(p00 - __uint_as_float(hi));
            hi = f2tf32(p01); PHI[(j0+1)*FPAD + mr] = hi; PLO[(j0+1)*FPAD + mr] = f2tf32(p01 - __uint_as_float(hi));
            hi = f2tf32(p10); PHI[j0*FPAD + mr+8] = hi;   PLO[j0*FPAD + mr+8]   = f2tf32(p10 - __uint_as_float(hi));
            hi = f2tf32(p11); PHI[(j0+1)*FPAD + mr+8] = hi; PLO[(j0+1)*FPAD + mr+8] = f2tf32(p11 - __uint_as_float(hi));
        }
        ps0 += __shfl_xor_sync(0xffffffffu, ps0, 1);
        ps0 += __shfl_xor_sync(0xffffffffu, ps0, 2);
        ps1 += __shfl_xor_sync(0xffffffffu, ps1, 1);
        ps1 += __shfl_xor_sync(0xffffffffu, ps1, 2);
        if (t4 == 0) {
            SSUM[mr*2 + wx] = ps0;
            SSUM[(mr+8)*2 + wx] = ps1;
        }

        // rescale accumulators
        #pragma unroll
        for (int nj = 0; nj < 4; nj++) {
            acc[nj][0] *= corr0; acc[nj][1] *= corr0;
            acc[nj][2] *= corr1; acc[nj][3] *= corr1;
        }
        __syncthreads();

        l0 = l0*corr0 + SSUM[mr*2] + SSUM[mr*2+1];
        l1 = l1*corr1 + SSUM[(mr+8)*2] + SSUM[(mr+8)*2+1];

        // ---- acc += P @ V (compensated) ----
        #pragma unroll
        for (int kk = 0; kk < 64; kk += 8) {
            unsigned ahi[4], alo[4];
            ahi[0] = PHI[(kk+t4)*FPAD + mr];
            ahi[1] = PHI[(kk+t4)*FPAD + mr + 8];
            ahi[2] = PHI[(kk+t4+4)*FPAD + mr];
            ahi[3] = PHI[(kk+t4+4)*FPAD + mr + 8];
            alo[0] = PLO[(kk+t4)*FPAD + mr];
            alo[1] = PLO[(kk+t4)*FPAD + mr + 8];
            alo[2] = PLO[(kk+t4+4)*FPAD + mr];
            alo[3] = PLO[(kk+t4+4)*FPAD + mr + 8];
            #pragma unroll
            for (int nj = 0; nj < 4; nj++) {
                int nc = wx*32 + nj*8 + g;
                unsigned bhi[2] = { VHI[(kk+t4)*FPAD + nc], VHI[(kk+t4+4)*FPAD + nc] };
                unsigned blo[2] = { VLO[(kk+t4)*FPAD + nc], VLO[(kk+t4+4)*FPAD + nc] };
                mma_tf32(acc[nj], ahi, bhi);
                mma_tf32(acc[nj], alo, bhi);
                mma_tf32(acc[nj], ahi, blo);
            }
        }
        __syncthreads();
    }

    // epilogue
    float inv0 = 1.f / l0, inv1 = 1.f / l1;
    #pragma unroll
    for (int nj = 0; nj < 4; nj++) {
        int col = h*oColMul + oColAdd + wx*32 + nj*8 + 2*t4;
        long r0 = (long)(qrow0 + mr)*ostride + col;
        long r1 = (long)(qrow0 + mr + 8)*ostride + col;
        *(float2*)&Out[r0] = make_float2(acc[nj][0]*inv0, acc[nj][1]*inv0);
        *(float2*)&Out[r1] = make_float2(acc[nj][2]*inv1, acc[nj][3]*inv1);
    }
}

// ---------------- memories copy ----------------
__global__ void memories_kernel(const float* __restrict__ qkv, float* __restrict__ out)
{
    int idx = blockIdx.x*256 + threadIdx.x;
    if (idx >= 2*HEADS*WIDTH*HD) return;
    int d = idx & 63;
    int i = (idx >> 6) & 511;
    int h = (idx >> 15) & 15;
    int s = idx >> 19;
    out[idx] = qkv[(long)(3584+i)*3072 + (s ? 2048 : 1024) + h*HD + d];
}

// ---------------- new_states ----------------
__global__ void newstates_kernel(const float* __restrict__ gz, const float* __restrict__ bg,
        const float* __restrict__ beta, const float* __restrict__ init_state,
        float* __restrict__ out)
{
    int idx = blockIdx.x*256 + threadIdx.x;
    if (idx >= NST*DIMM) return;
    int c = idx & (DIMM-1);
    float sig = 1.f/(1.f+expf(-beta[c]));
    float z = gz[idx] + bg[c];
    out[idx] = sig*z + (1.f-sig)*init_state[idx];
}

// ---------------- host launch ----------------
static float* symaddr(const void* s)
{
    void* p = nullptr;
    cudaGetSymbolAddress(&p, s);
    return (float*)p;
}

extern "C" void kernel_launch(void* const* d_in, const int* in_sizes, int n_in,
                              void* d_out, int out_size)
{
    const float* x       = (const float*)d_in[0];
    const float* bias    = (const float*)d_in[1];
    const float* gamma   = (const float*)d_in[2];
    const float* w_qkv   = (const float*)d_in[3];
    const float* q_scale = (const float*)d_in[4];
    const float* k_scale = (const float*)d_in[5];
    const float* w_out   = (const float*)d_in[6];
    const float* s_gamma = (const float*)d_in[7];
    const float* w_q2s   = (const float*)d_in[8];
    const float* w_qfs   = (const float*)d_in[9];
    const float* w_sqkv  = (const float*)d_in[10];
    const float* init_st = (const float*)d_in[11];
    const float* pos_ids = (const float*)d_in[12];
    const float* w_sout  = (const float*)d_in[13];
    const float* ts_q    = (const float*)d_in[14];
    const float* ts_k    = (const float*)d_in[15];
    const float* ss_q    = (const float*)d_in[16];
    const float* ss_k    = (const float*)d_in[17];
    const float* fs_q    = (const float*)d_in[18];
    const float* fs_k    = (const float*)d_in[19];
    const float* w_gate  = (const float*)d_in[20];
    const float* b_gate  = (const float*)d_in[21];
    const float* beta    = (const float*)d_in[22];
    float* out = (float*)d_out;

    float* xn   = symaddr(g_xn);
    float* qkv  = symaddr(g_qkv);
    float* q2s  = symaddr(g_q2s);
    float* sqkv = symaddr(g_state_qkv);
    float* st   = symaddr(g_st);
    float* qfsr = symaddr(g_qfs_raw);
    float* qnm  = symaddr(g_qn_main);
    float* knm  = symaddr(g_kn_main);
    float* qnts = symaddr(g_qn_ts);
    float* knts = symaddr(g_kn_ts);
    float* qnss = symaddr(g_qn_ss);
    float* knss = symaddr(g_kn_ss);
    float* qnfs = symaddr(g_qn_fs);
    float* knfs = symaddr(g_kn_fs);
    float* aout = symaddr(g_attn_out);
    float* tout = symaddr(g_ts_out);
    float* scat = symaddr(g_state_cat);
    float* so   = symaddr(g_so);
    float* zb   = symaddr(g_z);

    cudaFuncSetAttribute(flashmma, cudaFuncAttributeMaxDynamicSharedMemorySize, FLASH_SMEM);

    // 1) layernorms
    ln_kernel<<<NSEQ, 256>>>(x, gamma, nullptr, xn);
    ln_kernel<<<NST, 256>>>(init_st, s_gamma, pos_ids, st);

    // 2) projections (TF32 tensor cores)
    tgemm<<<dim3(3072/128, NSEQ/128), 256>>>(xn, w_qkv, qkv, NSEQ, 3072, DIMM, 0);
    tgemm<<<dim3(DIMM/128, NSEQ/128), 256>>>(xn, w_q2s, q2s, NSEQ, DIMM, DIMM, 0);
    tgemm<<<dim3(3072/128, NST/128), 256>>>(init_st, w_sqkv, sqkv, NST, 3072, DIMM, 0);
    tgemm<<<dim3(DIMM/128, NST/128), 256>>>(st, w_qfs, qfsr, NST, DIMM, DIMM, 0);

    // 3) l2norm + scale, head-major
    norm_heads<<<dim3(NSEQ, HEADS), 64>>>(qkv, 3072, 0,    0,    q_scale, qnm,  NSEQ);
    norm_heads<<<dim3(NSEQ, HEADS), 64>>>(qkv, 3072, 1024, 0,    k_scale, knm,  NSEQ);
    norm_heads<<<dim3(NSEQ, HEADS), 64>>>(q2s, 1024, 0,    0,    ts_q,    qnts, NSEQ);
    norm_heads<<<dim3(NST,  HEADS), 64>>>(sqkv, 3072, 1024, 0,   ts_k,    knts, NST);
    norm_heads<<<dim3(NST,  HEADS), 64>>>(sqkv, 3072, 0,    0,   ss_q,    qnss, NST);
    norm_heads<<<dim3(NST,  HEADS), 64>>>(sqkv, 3072, 1024, 0,   ss_k,    knss, NST);
    norm_heads<<<dim3(NST,  HEADS), 64>>>(qfsr, 1024, 0,    0,   fs_q,    qnfs, NST);
    norm_heads<<<dim3(NST,  HEADS), 64>>>(qkv,  3072, 1024, 3584, fs_k,   knfs, NST);

    // 4) fused attentions (compensated TF32 MMA)
    flashmma<<<dim3(WIDTH/64, HEADS*NW), 256, FLASH_SMEM>>>(
        qnm, NSEQ, knm, NSEQ, qkv, 3072, HD, 2048, 0, bias,
        aout, DIMM, HD, 0, KEYW, NW);
    flashmma<<<dim3(NSEQ/64, HEADS), 256, FLASH_SMEM>>>(
        qnts, NSEQ, knts, NST, sqkv, 3072, HD, 2048, 0, nullptr,
        tout, DIMM, HD, 0, NST, 1);
    flashmma<<<dim3(NST/64, HEADS), 256, FLASH_SMEM>>>(
        qnss, NST, knss, NST, sqkv, 3072, HD, 2048, 0, nullptr,
        scat, 2*DIMM, 2*HD, 0, NST, 1);
    flashmma<<<dim3(NST/64, HEADS), 256, FLASH_SMEM>>>(
        qnfs, NST, knfs, NST, qkv, 3072, HD, 2048, 3584, nullptr,
        scat, 2*DIMM, 2*HD, HD, NST, 1);

    // 5) output projections
    tgemm<<<dim3(DIMM/128, NSEQ/128), 256>>>(aout, w_out, out, NSEQ, DIMM, DIMM, 0);
    tgemm<<<dim3(DIMM/128, NSEQ/128), 256>>>(tout, w_out + (long)DIMM*DIMM, out, NSEQ, DIMM, DIMM, 1);

    // 6) memories
    memories_kernel<<<(2*HEADS*WIDTH*HD)/256, 256>>>(qkv, out + (long)NSEQ*DIMM);

    // 7) state output path
    tgemm<<<dim3(DIMM/128, NST/128), 256>>>(scat, w_sout, so, NST, DIMM, 2*DIMM, 0);
    tgemm<<<dim3(DIMM/128, NST/128), 256>>>(so, w_gate, zb, NST, DIMM, DIMM, 0);
    newstates_kernel<<<(NST*DIMM)/256, 256>>>(zb, b_gate, beta, init_st,
            out + (long)NSEQ*DIMM + 2*HEADS*WIDTH*HD);
}